// round 6
// baseline (speedup 1.0000x reference)
#include <cuda_runtime.h>

#define NN   4096
#define FIN  128
#define FOUT 64
#define NH   8
#define CT   1024            // 512 h-cols + 512 skip-cols
#define SLOPE 0.2f

// ---------------- scratch (device globals; no allocations) ----------------
__device__ float    g_W[FIN * CT];            // packed weights [128][1024]
__device__ float    g_hs[NN * CT];            // [n][1024]: 0..511 = h per head, 512..1023 = skip
__device__ float    g_ssrc[NH * NN];
__device__ float    g_sdst[NH * NN];
__device__ unsigned g_mask[NN * (NN / 32)];   // adjacency bitmask [4096][128 words]
__device__ float    g_attn[NH * NN * FOUT];   // per-head attention output

// ---------------- pack proj + skip_w^T into one [128][1024] weight --------
__global__ void k_pack_w(const float* __restrict__ proj, const float* __restrict__ skw) {
    int idx = blockIdx.x * 256 + threadIdx.x;          // 0..131071
    int k = idx >> 10, c = idx & 1023;
    float v;
    if (c < 512) v = proj[(c >> 6) * (FIN * FOUT) + k * FOUT + (c & 63)];
    else         v = skw[(c - 512) * FIN + k];
    g_W[idx] = v;
}

// ---------------- adjacency bitmask via warp ballot -----------------------
__global__ void k_mask(const float* __restrict__ topo) {
    int task = blockIdx.x * 8 + (threadIdx.x >> 5);    // warp task id
    int lane = threadIdx.x & 31;
    int i = task >> 7, w = task & 127;
    float v = topo[i * NN + w * 32 + lane];
    unsigned m = __ballot_sync(0xffffffffu, v > -1e8f);
    if (lane == 0) g_mask[i * 128 + w] = m;
}

// ---------------- GEMM: g_hs = x[4096x128] @ g_W[128x1024] ----------------
__global__ void __launch_bounds__(256) k_gemm(const float* __restrict__ x) {
    __shared__ float sX[64][68];    // [row][k-half] padded (+4) against bank conflicts
    __shared__ float sB[64][64];    // [k-half][c]
    int tid = threadIdx.x;
    int bm = blockIdx.x, bn = blockIdx.y;
    int tr = tid >> 4, tc = tid & 15;       // 16x16 threads, 4x4 micro-tile
    float4 acc0 = make_float4(0.f,0.f,0.f,0.f);
    float4 acc1 = acc0, acc2 = acc0, acc3 = acc0;
    for (int kk = 0; kk < 2; kk++) {
        __syncthreads();
        #pragma unroll
        for (int it = 0; it < 4; it++) {
            int idx = tid + it * 256;       // 64 rows x 16 float4
            int row = idx >> 4, k4 = idx & 15;
            float4 v = *(const float4*)(x + (bm * 64 + row) * FIN + kk * 64 + k4 * 4);
            *(float4*)(&sX[row][k4 * 4]) = v;
        }
        #pragma unroll
        for (int it = 0; it < 4; it++) {
            int idx = tid + it * 256;       // 64 k x 16 float4
            int k = idx >> 4, c4 = idx & 15;
            float4 v = *(const float4*)(g_W + (kk * 64 + k) * CT + bn * 64 + c4 * 4);
            *(float4*)(&sB[k][c4 * 4]) = v;
        }
        __syncthreads();
        #pragma unroll 8
        for (int k = 0; k < 64; k++) {
            float4 b = *(const float4*)(&sB[k][tc * 4]);
            float a0 = sX[tr * 4 + 0][k];
            float a1 = sX[tr * 4 + 1][k];
            float a2 = sX[tr * 4 + 2][k];
            float a3 = sX[tr * 4 + 3][k];
            acc0.x += a0 * b.x; acc0.y += a0 * b.y; acc0.z += a0 * b.z; acc0.w += a0 * b.w;
            acc1.x += a1 * b.x; acc1.y += a1 * b.y; acc1.z += a1 * b.z; acc1.w += a1 * b.w;
            acc2.x += a2 * b.x; acc2.y += a2 * b.y; acc2.z += a2 * b.z; acc2.w += a2 * b.w;
            acc3.x += a3 * b.x; acc3.y += a3 * b.y; acc3.z += a3 * b.z; acc3.w += a3 * b.w;
        }
    }
    float* dst = g_hs + (bm * 64 + tr * 4) * CT + bn * 64 + tc * 4;
    *(float4*)(dst + 0 * CT) = acc0;
    *(float4*)(dst + 1 * CT) = acc1;
    *(float4*)(dst + 2 * CT) = acc2;
    *(float4*)(dst + 3 * CT) = acc3;
}

// ---------------- s_src / s_dst: per-(head,node) dot products -------------
__global__ void k_svec(const float* __restrict__ wsrc, const float* __restrict__ wdst) {
    int gw = blockIdx.x * 8 + (threadIdx.x >> 5);      // 0..32767
    int lane = threadIdx.x & 31;
    int h = gw >> 12, n = gw & 4095;
    float2 hv = *(const float2*)(g_hs + n * CT + h * 64 + lane * 2);
    float2 a  = *(const float2*)(wsrc + h * 64 + lane * 2);
    float2 b  = *(const float2*)(wdst + h * 64 + lane * 2);
    float ss = hv.x * a.x + hv.y * a.y;
    float sd = hv.x * b.x + hv.y * b.y;
    #pragma unroll
    for (int o = 16; o > 0; o >>= 1) {
        ss += __shfl_xor_sync(0xffffffffu, ss, o);
        sd += __shfl_xor_sync(0xffffffffu, sd, o);
    }
    if (lane == 0) { g_ssrc[h * NN + n] = ss; g_sdst[h * NN + n] = sd; }
}

// ---------------- main: masked softmax + sparse aggregation ---------------
// grid (32 i-tiles, 8 heads); block 256 = 8 warps; warp owns 16 rows; lane owns 2 outs
__global__ void __launch_bounds__(256, 2) k_attn() {
    __shared__ float    sh[128 * 64];     // h tile [j][o], 32 KB
    __shared__ float    sdst[128];
    __shared__ unsigned smask[512];       // [row][4 words]
    int tid = threadIdx.x, lane = tid & 31, wid = tid >> 5;
    int head  = blockIdx.y;
    int ibase = blockIdx.x * 128;
    int rbase = wid * 16;

    float2 acc[16];
    float  rs[16], ssr[16];
    #pragma unroll
    for (int r = 0; r < 16; r++) {
        acc[r] = make_float2(0.f, 0.f);
        rs[r] = 0.f;
        ssr[r] = g_ssrc[head * NN + ibase + rbase + r];
    }

    for (int jt = 0; jt < 32; jt++) {
        __syncthreads();
        #pragma unroll
        for (int it = 0; it < 8; it++) {
            int idx = tid + it * 256;     // 128 rows x 16 float4
            int jj = idx >> 4, o4 = idx & 15;
            float4 v = *(const float4*)(g_hs + (jt * 128 + jj) * CT + head * 64 + o4 * 4);
            *(float4*)(sh + jj * 64 + o4 * 4) = v;
        }
        if (tid < 128) sdst[tid] = g_sdst[head * NN + jt * 128 + tid];
        for (int s = tid; s < 512; s += 256)
            smask[s] = g_mask[(ibase + (s >> 2)) * 128 + jt * 4 + (s & 3)];
        __syncthreads();

        #pragma unroll
        for (int r = 0; r < 16; r++) {
            unsigned mq0 = smask[(rbase + r) * 4 + 0];
            unsigned mq1 = smask[(rbase + r) * 4 + 1];
            unsigned mq2 = smask[(rbase + r) * 4 + 2];
            unsigned mq3 = smask[(rbase + r) * 4 + 3];
            if (!(mq0 | mq1 | mq2 | mq3)) continue;
            float ssrc = ssr[r];
            // dense score/exp: each lane covers j = q*32+lane (masked select; exp on MUFU)
            float v0 = ssrc + sdst[lane];
            float v1 = ssrc + sdst[32 + lane];
            float v2 = ssrc + sdst[64 + lane];
            float v3 = ssrc + sdst[96 + lane];
            v0 = fmaxf(v0, SLOPE * v0);
            v1 = fmaxf(v1, SLOPE * v1);
            v2 = fmaxf(v2, SLOPE * v2);
            v3 = fmaxf(v3, SLOPE * v3);
            float p0 = ((mq0 >> lane) & 1u) ? __expf(v0) : 0.f;
            float p1 = ((mq1 >> lane) & 1u) ? __expf(v1) : 0.f;
            float p2 = ((mq2 >> lane) & 1u) ? __expf(v2) : 0.f;
            float p3 = ((mq3 >> lane) & 1u) ? __expf(v3) : 0.f;
            rs[r] += (p0 + p1) + (p2 + p3);

            // sparse aggregation: warp-uniform bit scan, shfl-broadcast of p
            float ax = acc[r].x, ay = acc[r].y;
            unsigned m;
            m = mq0;
            while (m) {
                int b = __ffs(m) - 1; m &= m - 1;
                float p = __shfl_sync(0xffffffffu, p0, b);
                float2 hv = *(const float2*)(sh + b * 64 + lane * 2);
                ax += p * hv.x; ay += p * hv.y;
            }
            m = mq1;
            while (m) {
                int b = __ffs(m) - 1; m &= m - 1;
                float p = __shfl_sync(0xffffffffu, p1, b);
                float2 hv = *(const float2*)(sh + (32 + b) * 64 + lane * 2);
                ax += p * hv.x; ay += p * hv.y;
            }
            m = mq2;
            while (m) {
                int b = __ffs(m) - 1; m &= m - 1;
                float p = __shfl_sync(0xffffffffu, p2, b);
                float2 hv = *(const float2*)(sh + (64 + b) * 64 + lane * 2);
                ax += p * hv.x; ay += p * hv.y;
            }
            m = mq3;
            while (m) {
                int b = __ffs(m) - 1; m &= m - 1;
                float p = __shfl_sync(0xffffffffu, p3, b);
                float2 hv = *(const float2*)(sh + (96 + b) * 64 + lane * 2);
                ax += p * hv.x; ay += p * hv.y;
            }
            acc[r].x = ax; acc[r].y = ay;
        }
    }

    #pragma unroll
    for (int r = 0; r < 16; r++) {
        float s = rs[r];
        #pragma unroll
        for (int o = 16; o > 0; o >>= 1) s += __shfl_xor_sync(0xffffffffu, s, o);
        float inv = 1.0f / s;
        int i = ibase + rbase + r;
        float2 res;
        res.x = acc[r].x * inv;
        res.y = acc[r].y * inv;
        *(float2*)(g_attn + (head * NN + i) * FOUT + lane * 2) = res;
    }
}

// ---------------- finalize: mean over heads (+ skip), LeakyReLU -----------
__global__ void k_final(float* __restrict__ out) {
    int idx = blockIdx.x * 256 + threadIdx.x;          // 0..262143
    int i = idx >> 6, o = idx & 63;
    float s = 0.f;
    #pragma unroll
    for (int h = 0; h < NH; h++)
        s += g_attn[(h * NN + i) * FOUT + o] + g_hs[i * CT + 512 + h * 64 + o];
    s *= 0.125f;
    out[idx] = fmaxf(s, SLOPE * s);
}

// ---------------- launch ---------------------------------------------------
extern "C" void kernel_launch(void* const* d_in, const int* in_sizes, int n_in,
                              void* d_out, int out_size) {
    const float* x     = (const float*)d_in[0];   // [4096,128]
    const float* topo  = (const float*)d_in[1];   // [4096,4096]
    const float* proj  = (const float*)d_in[2];   // [8,128,64]
    const float* wsrc  = (const float*)d_in[3];   // [8,64]
    const float* wdst  = (const float*)d_in[4];   // [8,64]
    const float* skw   = (const float*)d_in[5];   // [512,128]
    float* out = (float*)d_out;                   // [4096,64]

    k_pack_w<<<512, 256>>>(proj, skw);
    k_mask<<<65536, 256>>>(topo);
    k_gemm<<<dim3(64, 16), 256>>>(x);
    k_svec<<<4096, 256>>>(wsrc, wdst);
    k_attn<<<dim3(32, 8), 256>>>();
    k_final<<<1024, 256>>>(out);
}

// round 8
// speedup vs baseline: 2.2946x; 2.2946x over previous
#include <cuda_runtime.h>
#include <cstdint>

#define NN   4096
#define FIN  128
#define FOUT 64
#define NH   8
#define CT   1024
#define SLOPE 0.2f
#define BSTRIDE 132   // 128 + 4 pad: makes B-fragment LDS conflict-free

// ---------------- scratch (device globals; no allocations) ----------------
__device__ float    g_W[FIN * CT];
__device__ float    g_hs[NN * CT];            // [n][1024]: 0..511 h per head, 512..1023 skip
__device__ float    g_hT[NH * FOUT * NN];     // [h][o][j], values pre-rounded to tf32
__device__ float    g_ssrc[NH * NN];
__device__ float    g_sdst[NH * NN];
__device__ unsigned g_maskT[(NN / 32) * NN];  // [word w][i] transposed adjacency bitmask
__device__ float    g_attn[NH * NN * FOUT];

__device__ __forceinline__ uint32_t smem_u32(const void* p) {
    uint32_t a;
    asm("{ .reg .u64 t; cvta.to.shared.u64 t, %1; cvt.u32.u64 %0, t; }" : "=r"(a) : "l"(p));
    return a;
}

// ---------------- pack proj + skip_w^T into one [128][1024] weight --------
__global__ void k_pack_w(const float* __restrict__ proj, const float* __restrict__ skw) {
    int idx = blockIdx.x * 256 + threadIdx.x;
    int k = idx >> 10, c = idx & 1023;
    float v;
    if (c < 512) v = proj[(c >> 6) * (FIN * FOUT) + k * FOUT + (c & 63)];
    else         v = skw[(c - 512) * FIN + k];
    g_W[idx] = v;
}

// ---------------- adjacency bitmask (transposed: [word][i]) ---------------
__global__ void k_mask(const float* __restrict__ topo) {
    int task = blockIdx.x * 8 + (threadIdx.x >> 5);
    int lane = threadIdx.x & 31;
    int i = task >> 7, w = task & 127;
    float v = topo[i * NN + w * 32 + lane];
    unsigned m = __ballot_sync(0xffffffffu, v > -1e8f);
    if (lane == 0) g_maskT[w * NN + i] = m;
}

// ---------------- GEMM: g_hs = x[4096x128] @ g_W[128x1024] ----------------
__global__ void __launch_bounds__(256) k_gemm(const float* __restrict__ x) {
    __shared__ float sX[64][68];
    __shared__ float sB[64][64];
    int tid = threadIdx.x;
    int bm = blockIdx.x, bn = blockIdx.y;
    int tr = tid >> 4, tc = tid & 15;
    float4 acc0 = make_float4(0.f,0.f,0.f,0.f);
    float4 acc1 = acc0, acc2 = acc0, acc3 = acc0;
    for (int kk = 0; kk < 2; kk++) {
        __syncthreads();
        #pragma unroll
        for (int it = 0; it < 4; it++) {
            int idx = tid + it * 256;
            int row = idx >> 4, k4 = idx & 15;
            float4 v = *(const float4*)(x + (bm * 64 + row) * FIN + kk * 64 + k4 * 4);
            *(float4*)(&sX[row][k4 * 4]) = v;
        }
        #pragma unroll
        for (int it = 0; it < 4; it++) {
            int idx = tid + it * 256;
            int k = idx >> 4, c4 = idx & 15;
            float4 v = *(const float4*)(g_W + (kk * 64 + k) * CT + bn * 64 + c4 * 4);
            *(float4*)(&sB[k][c4 * 4]) = v;
        }
        __syncthreads();
        #pragma unroll 8
        for (int k = 0; k < 64; k++) {
            float4 b = *(const float4*)(&sB[k][tc * 4]);
            float a0 = sX[tr * 4 + 0][k];
            float a1 = sX[tr * 4 + 1][k];
            float a2 = sX[tr * 4 + 2][k];
            float a3 = sX[tr * 4 + 3][k];
            acc0.x += a0 * b.x; acc0.y += a0 * b.y; acc0.z += a0 * b.z; acc0.w += a0 * b.w;
            acc1.x += a1 * b.x; acc1.y += a1 * b.y; acc1.z += a1 * b.z; acc1.w += a1 * b.w;
            acc2.x += a2 * b.x; acc2.y += a2 * b.y; acc2.z += a2 * b.z; acc2.w += a2 * b.w;
            acc3.x += a3 * b.x; acc3.y += a3 * b.y; acc3.z += a3 * b.z; acc3.w += a3 * b.w;
        }
    }
    float* dst = g_hs + (bm * 64 + tr * 4) * CT + bn * 64 + tc * 4;
    *(float4*)(dst + 0 * CT) = acc0;
    *(float4*)(dst + 1 * CT) = acc1;
    *(float4*)(dst + 2 * CT) = acc2;
    *(float4*)(dst + 3 * CT) = acc3;
}

// ---------------- s_src / s_dst dot products ------------------------------
__global__ void k_svec(const float* __restrict__ wsrc, const float* __restrict__ wdst) {
    int gw = blockIdx.x * 8 + (threadIdx.x >> 5);
    int lane = threadIdx.x & 31;
    int h = gw >> 12, n = gw & 4095;
    float2 hv = *(const float2*)(g_hs + n * CT + h * 64 + lane * 2);
    float2 a  = *(const float2*)(wsrc + h * 64 + lane * 2);
    float2 b  = *(const float2*)(wdst + h * 64 + lane * 2);
    float ss = hv.x * a.x + hv.y * a.y;
    float sd = hv.x * b.x + hv.y * b.y;
    #pragma unroll
    for (int o = 16; o > 0; o >>= 1) {
        ss += __shfl_xor_sync(0xffffffffu, ss, o);
        sd += __shfl_xor_sync(0xffffffffu, sd, o);
    }
    if (lane == 0) { g_ssrc[h * NN + n] = ss; g_sdst[h * NN + n] = sd; }
}

// ---------------- transpose h (and round to tf32): g_hT[h][o][j] ----------
__global__ void k_transp() {
    __shared__ float s[32][33];
    int h = blockIdx.z, ot = blockIdx.y, jt = blockIdx.x;
    int x = threadIdx.x, y = threadIdx.y;   // block (32, 8)
    #pragma unroll
    for (int r = 0; r < 4; r++) {
        int j = jt * 32 + y + r * 8;
        s[y + r * 8][x] = g_hs[j * CT + h * 64 + ot * 32 + x];
    }
    __syncthreads();
    #pragma unroll
    for (int r = 0; r < 4; r++) {
        int o = ot * 32 + y + r * 8;
        float v = s[x][y + r * 8];
        uint32_t u;
        asm("cvt.rna.tf32.f32 %0, %1;" : "=r"(u) : "f"(v));   // round-to-nearest tf32
        g_hT[(h * 64 + o) * NN + jt * 32 + x] = __uint_as_float(u);
    }
}

// ---------------- B tile loader: hT[64 o][128 j] -> smem (pad-132) --------
__device__ __forceinline__ void load_btile(const float* __restrict__ hT, int jt,
                                           uint32_t bufb, int tid) {
    #pragma unroll
    for (int c = 0; c < 8; c++) {
        int idx = tid + c * 256;            // 64 rows x 32 float4
        int o = idx >> 5, f4 = idx & 31;
        uint32_t dst = bufb + (uint32_t)(o * (BSTRIDE * 4) + f4 * 16);
        const float* src = hT + o * NN + jt * 128 + f4 * 4;
        asm volatile("cp.async.cg.shared.global [%0], [%1], 16;"
                     :: "r"(dst), "l"(src) : "memory");
    }
}

// ---------------- masked-exp directly in mma A-fragment layout ------------
__device__ __forceinline__ uint32_t pgen(float ssrc, float sd, unsigned m, int sh,
                                         float& rs) {
    float v = ssrc + sd;
    v = fmaxf(v, SLOPE * v);
    float e = __expf(v);
    float p = ((m >> sh) & 1u) ? e : 0.f;
    uint32_t u;
    asm("cvt.rna.tf32.f32 %0, %1;" : "=r"(u) : "f"(p));
    rs += __uint_as_float(u);               // denominator uses same rounded value
    return u;
}

// ---------------- main attention: P-gen + P@h via mma.sync tf32 -----------
// grid (32 i-tiles, 8 heads), block 256 = 8 warps; warp owns 16 i-rows.
__global__ void __launch_bounds__(256, 2) k_attn() {
    extern __shared__ float sB[];           // 2 x [64][BSTRIDE]
    __shared__ float    s_sdst[128];
    __shared__ unsigned smask[512];         // [row][word q]

    int tid = threadIdx.x, lane = tid & 31, wid = tid >> 5;
    int g = lane >> 2, t = lane & 3;
    int head = blockIdx.y, ibase = blockIdx.x * 128;
    int r1 = wid * 16 + g, r2 = r1 + 8;

    float ssr1 = g_ssrc[head * NN + ibase + r1];
    float ssr2 = g_ssrc[head * NN + ibase + r2];
    const float* hT = g_hT + (size_t)head * (FOUT * NN);
    uint32_t sb_u32 = smem_u32(sB);

    float acc[8][4];
    #pragma unroll
    for (int nt = 0; nt < 8; nt++)
        acc[nt][0] = acc[nt][1] = acc[nt][2] = acc[nt][3] = 0.f;
    float rs1 = 0.f, rs2 = 0.f;

    load_btile(hT, 0, sb_u32, tid);
    asm volatile("cp.async.commit_group;" ::: "memory");

    for (int jt = 0; jt < 32; jt++) {
        __syncthreads();                    // jt-1 compute done: stage area + buf free
        if (tid < 128) s_sdst[tid] = g_sdst[head * NN + jt * 128 + tid];
        #pragma unroll
        for (int s = tid; s < 512; s += 256)
            smask[(s & 127) * 4 + (s >> 7)] =
                g_maskT[(jt * 4 + (s >> 7)) * NN + ibase + (s & 127)];
        if (jt < 31)
            load_btile(hT, jt + 1, sb_u32 + (uint32_t)(((jt + 1) & 1) * (64 * BSTRIDE * 4)), tid);
        asm volatile("cp.async.commit_group;" ::: "memory");
        asm volatile("cp.async.wait_group 1;" ::: "memory");   // tile jt resident
        __syncthreads();

        const float* buf = sB + (jt & 1) * (64 * BSTRIDE);

        #pragma unroll
        for (int q = 0; q < 4; q++) {
            unsigned mw1 = smask[r1 * 4 + q];
            unsigned mw2 = smask[r2 * 4 + q];
            #pragma unroll
            for (int kc2 = 0; kc2 < 4; kc2++) {
                int kc = q * 4 + kc2;
                float sd0 = s_sdst[kc * 8 + t];
                float sd4 = s_sdst[kc * 8 + t + 4];
                int sh0 = kc2 * 8 + t;
                uint32_t a0 = pgen(ssr1, sd0, mw1, sh0, rs1);
                uint32_t a1 = pgen(ssr2, sd0, mw2, sh0, rs2);
                uint32_t a2 = pgen(ssr1, sd4, mw1, sh0 + 4, rs1);
                uint32_t a3 = pgen(ssr2, sd4, mw2, sh0 + 4, rs2);
                #pragma unroll
                for (int nt = 0; nt < 8; nt++) {
                    uint32_t b0 = __float_as_uint(buf[(nt * 8 + g) * BSTRIDE + kc * 8 + t]);
                    uint32_t b1 = __float_as_uint(buf[(nt * 8 + g) * BSTRIDE + kc * 8 + t + 4]);
                    asm volatile(
                        "mma.sync.aligned.m16n8k8.row.col.f32.tf32.tf32.f32 "
                        "{%0,%1,%2,%3}, {%4,%5,%6,%7}, {%8,%9}, {%0,%1,%2,%3};"
                        : "+f"(acc[nt][0]), "+f"(acc[nt][1]),
                          "+f"(acc[nt][2]), "+f"(acc[nt][3])
                        : "r"(a0), "r"(a1), "r"(a2), "r"(a3), "r"(b0), "r"(b1));
                }
            }
        }
    }

    // row-sum reduce over the 4 lanes sharing each row, normalize, store
    rs1 += __shfl_xor_sync(0xffffffffu, rs1, 1);
    rs1 += __shfl_xor_sync(0xffffffffu, rs1, 2);
    rs2 += __shfl_xor_sync(0xffffffffu, rs2, 1);
    rs2 += __shfl_xor_sync(0xffffffffu, rs2, 2);
    float inv1 = 1.0f / rs1, inv2 = 1.0f / rs2;

    float* o1 = g_attn + (size_t)(head * NN + ibase + r1) * FOUT + 2 * t;
    float* o2 = g_attn + (size_t)(head * NN + ibase + r2) * FOUT + 2 * t;
    #pragma unroll
    for (int nt = 0; nt < 8; nt++) {
        float2 v1; v1.x = acc[nt][0] * inv1; v1.y = acc[nt][1] * inv1;
        float2 v2; v2.x = acc[nt][2] * inv2; v2.y = acc[nt][3] * inv2;
        *(float2*)(o1 + nt * 8) = v1;
        *(float2*)(o2 + nt * 8) = v2;
    }
}

// ---------------- finalize: mean over heads (+ skip), LeakyReLU -----------
__global__ void k_final(float* __restrict__ out) {
    int idx = blockIdx.x * 256 + threadIdx.x;
    int i = idx >> 6, o = idx & 63;
    float s = 0.f;
    #pragma unroll
    for (int h = 0; h < NH; h++)
        s += g_attn[(h * NN + i) * FOUT + o] + g_hs[i * CT + 512 + h * 64 + o];
    s *= 0.125f;
    out[idx] = fmaxf(s, SLOPE * s);
}

// ---------------- launch ---------------------------------------------------
extern "C" void kernel_launch(void* const* d_in, const int* in_sizes, int n_in,
                              void* d_out, int out_size) {
    const float* x    = (const float*)d_in[0];   // [4096,128]
    const float* topo = (const float*)d_in[1];   // [4096,4096]
    const float* proj = (const float*)d_in[2];   // [8,128,64]
    const float* wsrc = (const float*)d_in[3];   // [8,64]
    const float* wdst = (const float*)d_in[4];   // [8,64]
    const float* skw  = (const float*)d_in[5];   // [512,128]
    float* out = (float*)d_out;                  // [4096,64]

    k_pack_w<<<512, 256>>>(proj, skw);
    k_mask<<<65536, 256>>>(topo);
    k_gemm<<<dim3(64, 16), 256>>>(x);
    k_svec<<<4096, 256>>>(wsrc, wdst);
    k_transp<<<dim3(128, 2, 8), dim3(32, 8)>>>();

    cudaFuncSetAttribute(k_attn, cudaFuncAttributeMaxDynamicSharedMemorySize,
                         2 * 64 * BSTRIDE * 4);
    k_attn<<<dim3(32, 8), 256, 2 * 64 * BSTRIDE * 4>>>();

    k_final<<<1024, 256>>>(out);
}